// round 14
// baseline (speedup 1.0000x reference)
#include <cuda_runtime.h>
#include <cuda_fp16.h>
#include <cstdint>

// ============================================================================
// TwoTowerModel — 16 independent warps/CTA (4/SMSP), 32 rows/warp, fp16
// mma.sync, register GEMM1->GEMM2 handoff, coalesced 2-pass gather, single
// per-warp X buffer, warp-parity tower stagger. (baseline sm_103 ISA)
// ============================================================================

static constexpr int BATCH   = 524288;
static constexpr int NGROUPS = BATCH / 32;     // 16384 32-row groups
static constexpr int THREADS = 512;            // 16 warps, each owns a group stream
static constexpr int NCTAS   = 148;

// ---- shared memory layout (bytes) ----
static constexpr int OFF_X    = 0;             // per-warp fp16 X [16][32][64] swz, 64K
static constexpr int OFF_VEC  = 65536;         // first-tower normalized vec fp16, 64K
static constexpr int OFF_W1F  = 131072;        // W1 frags: [tower]*16K = 32K
static constexpr int OFF_W2F  = 163840;        // W2 frags: 32K
static constexpr int OFF_B1H  = 196608;        // half2[2][64] packed layer1 bias
static constexpr int OFF_B2   = 197120;        // float[2][64]
static constexpr int SMEM_TOTAL = 197632;

__device__ __forceinline__ uint32_t smem_u32(const void* p) {
    uint32_t a;
    asm("{ .reg .u64 t; cvta.to.shared.u64 t, %1; cvt.u32.u64 %0, t; }" : "=r"(a) : "l"(p));
    return a;
}
__device__ __forceinline__ void mma_f16(float* d, const uint32_t* a, uint32_t b0, uint32_t b1) {
    asm volatile("mma.sync.aligned.m16n8k16.row.col.f32.f16.f16.f32 "
        "{%0,%1,%2,%3}, {%4,%5,%6,%7}, {%8,%9}, {%0,%1,%2,%3};"
        : "+f"(d[0]), "+f"(d[1]), "+f"(d[2]), "+f"(d[3])
        : "r"(a[0]), "r"(a[1]), "r"(a[2]), "r"(a[3]), "r"(b0), "r"(b1));
}
__device__ __forceinline__ void ldm4(uint32_t* a, uint32_t addr) {
    asm volatile("ldmatrix.sync.aligned.m8n8.x4.shared.b16 {%0,%1,%2,%3}, [%4];"
        : "=r"(a[0]), "=r"(a[1]), "=r"(a[2]), "=r"(a[3]) : "r"(addr) : "memory");
}
__device__ __forceinline__ void lds128(uint32_t* q, uint32_t addr) {
    asm volatile("ld.shared.v4.b32 {%0,%1,%2,%3}, [%4];"
        : "=r"(q[0]), "=r"(q[1]), "=r"(q[2]), "=r"(q[3]) : "r"(addr));
}
__device__ __forceinline__ uint32_t packh2(float a, float b) {
    __half2 h = __floats2half2_rn(a, b);
    return *(uint32_t*)&h;
}
__device__ __forceinline__ uint32_t ep1h2(float a, float b, uint32_t bias2) {
    __half2 x = __floats2half2_rn(a, b);
    x = __hmax2(__hadd2(x, *(__half2*)&bias2), __half2(__float2half_rn(0.0f), __float2half_rn(0.0f)));
    return *(uint32_t*)&x;
}

__global__ __launch_bounds__(THREADS, 1)
void twotower_kernel(
    const int* __restrict__ user_ids, const int* __restrict__ item_ids,
    const float* __restrict__ user_table, const float* __restrict__ item_table,
    const float* __restrict__ uW1, const float* __restrict__ ub1,
    const float* __restrict__ uW2, const float* __restrict__ ub2,
    const float* __restrict__ iW1, const float* __restrict__ ib1,
    const float* __restrict__ iW2, const float* __restrict__ ib2,
    float* __restrict__ out)
{
    extern __shared__ char smem[];
    const uint32_t sb = smem_u32(smem);
    const int tid  = threadIdx.x;
    const int wid  = tid >> 5;
    const int lane = tid & 31;
    const int tg   = lane & 3;
    const int g    = lane >> 2;
    const int khalf = lane >> 4;

    // ============ stage weights as nt-paired mma B-fragments (fp16) ====
    for (int t = 0; t < 2; t++) {
        const float* gW1 = t ? iW1 : uW1;   // [64][128] row-major
        const float* gW2 = t ? iW2 : uW2;   // [128][64]
        const float* gb1 = t ? ib1 : ub1;
        const float* gb2 = t ? ib2 : ub2;
        for (int p = tid; p < 1024; p += THREADS) {       // W1: kt(4) x ntp(8) x lane(32)
            int kt = p >> 8, ntp = (p >> 5) & 7, ln = p & 31;
            int ltg = ln & 3, lg = ln >> 2;
            int k0 = kt * 16 + ltg * 2;
            uint32_t q[4];
#pragma unroll
            for (int s = 0; s < 2; s++) {
                int n = (2 * ntp + s) * 8 + lg;
                q[2 * s + 0] = packh2(__ldg(gW1 + k0 * 128 + n),       __ldg(gW1 + (k0 + 1) * 128 + n));
                q[2 * s + 1] = packh2(__ldg(gW1 + (k0 + 8) * 128 + n), __ldg(gW1 + (k0 + 9) * 128 + n));
            }
            *((uint4*)(smem + OFF_W1F + t * 16384) + p) = make_uint4(q[0], q[1], q[2], q[3]);
        }
        for (int p = tid; p < 1024; p += THREADS) {       // W2: kt(8) x ntp(4) x lane(32)
            int kt = p >> 7, ntp = (p >> 5) & 3, ln = p & 31;
            int ltg = ln & 3, lg = ln >> 2;
            int k0 = kt * 16 + ltg * 2;
            uint32_t q[4];
#pragma unroll
            for (int s = 0; s < 2; s++) {
                int n = (2 * ntp + s) * 8 + lg;
                q[2 * s + 0] = packh2(__ldg(gW2 + k0 * 64 + n),       __ldg(gW2 + (k0 + 1) * 64 + n));
                q[2 * s + 1] = packh2(__ldg(gW2 + (k0 + 8) * 64 + n), __ldg(gW2 + (k0 + 9) * 64 + n));
            }
            *((uint4*)(smem + OFF_W2F + t * 16384) + p) = make_uint4(q[0], q[1], q[2], q[3]);
        }
        if (tid < 64) {   // packed half2 layer-1 bias: idx = nt*4+tg
            int nt = tid >> 2, ltg = tid & 3;
            int c0 = nt * 8 + ltg * 2;
            ((uint32_t*)(smem + OFF_B1H))[t * 64 + tid] = packh2(__ldg(gb1 + c0), __ldg(gb1 + c0 + 1));
        }
        if (tid < 64)  ((float*)(smem + OFF_B2))[t * 64 + tid] = __ldg(gb2 + tid);
    }
    __syncthreads();

    const int pf = wid & 1;                   // parity: which tower goes first
    const int* idsF = pf ? item_ids : user_ids;
    const int* idsS = pf ? user_ids : item_ids;
    const float* tblF = pf ? item_table : user_table;
    const float* tblS = pf ? user_table : item_table;
    const uint32_t wofF = pf ? 16384u : 0u;
    const uint32_t wofS = 16384u - wofF;
    const uint32_t b1hF = (uint32_t)pf * 256u, b1hS = 256u - b1hF;
    const int b2F = pf * 64, b2S = 64 - b2F;

    const uint32_t xbase = sb + OFF_X + (uint32_t)wid * 4096u;   // warp's X slab
    const int rg = lane >> 3;                 // coalesced gather: row-in-group-of-4
    const int gs = lane & 7;                  // 16B sector within 128B line
    const int lr0 = lane & 15;                // ldmatrix local rows
    const int lr1 = lr0 + 16;
    const uint32_t l0b = (uint32_t)lr0 * 128, l1b = (uint32_t)lr1 * 128;
    const uint32_t l0x = (uint32_t)(lr0 & 7), l1x = (uint32_t)(lr1 & 7);

    const int gstride = (int)gridDim.x << 4;

    for (int gid = blockIdx.x * 16 + wid; gid < NGROUPS; gid += gstride) {
        const int rowbase = gid * 32;
        int idF = __ldg(idsF + rowbase + lane);
        int idS = __ldg(idsS + rowbase + lane);

        // ---- gather+convert FIRST tower into X (2 passes of 16 rows) ----
#pragma unroll
        for (int p = 0; p < 2; p++) {
            float4 stg[8];
#pragma unroll
            for (int k = 0; k < 4; k++) {
                int idk = __shfl_sync(0xffffffffu, idF, p * 16 + k * 4 + rg);
                const float4* src = (const float4*)(tblF + (size_t)(uint32_t)idk * 64);
                stg[2 * k]     = __ldg(src + gs);
                stg[2 * k + 1] = __ldg(src + 8 + gs);
            }
#pragma unroll
            for (int k = 0; k < 4; k++) {
                int lrow = p * 16 + k * 4 + rg;
#pragma unroll
                for (int half = 0; half < 2; half++) {
                    float4 v = stg[2 * k + half];
                    uint32_t chunk = (uint32_t)(half * 4 + (gs >> 1));
                    uint32_t ad = (uint32_t)lrow * 128 + ((chunk ^ (uint32_t)(lrow & 7)) << 4) + (uint32_t)(gs & 1) * 8;
                    *(uint2*)(smem + (xbase - sb) + ad) = make_uint2(packh2(v.x, v.y), packh2(v.z, v.w));
                }
            }
        }
        __syncwarp();

        uint32_t hfrag[2][8][4];
        float acc2[2][8][4];

        // ================= FIRST tower =================
#pragma unroll
        for (int h = 0; h < 2; h++) {
            float acc1[2][8][4];
#pragma unroll
            for (int rb = 0; rb < 2; rb++)
#pragma unroll
                for (int i = 0; i < 8; i++)
#pragma unroll
                    for (int j = 0; j < 4; j++) acc1[rb][i][j] = 0.0f;
#pragma unroll
            for (int kt = 0; kt < 4; kt++) {
                uint32_t A0[4], A1[4];
                uint32_t chg = (uint32_t)(kt * 2 + khalf);
                ldm4(A0, xbase + l0b + ((chg ^ l0x) << 4));
                ldm4(A1, xbase + l1b + ((chg ^ l1x) << 4));
                uint32_t wb = sb + OFF_W1F + wofF + ((uint32_t)((kt * 8 + h * 4) * 32 + lane)) * 16;
#pragma unroll
                for (int i = 0; i < 4; i++) {
                    uint32_t q[4];
                    lds128(q, wb + (uint32_t)i * 512);
                    mma_f16(acc1[0][2 * i],     A0, q[0], q[1]);
                    mma_f16(acc1[0][2 * i + 1], A0, q[2], q[3]);
                    mma_f16(acc1[1][2 * i],     A1, q[0], q[1]);
                    mma_f16(acc1[1][2 * i + 1], A1, q[2], q[3]);
                }
            }
            const uint32_t* b1p = (const uint32_t*)(smem + OFF_B1H + b1hF);
#pragma unroll
            for (int rb = 0; rb < 2; rb++)
#pragma unroll
                for (int kp = 0; kp < 4; kp++) {
                    int lA = 2 * kp, lB = 2 * kp + 1;
                    uint32_t bA = b1p[(8 * h + lA) * 4 + tg];
                    uint32_t bB = b1p[(8 * h + lB) * 4 + tg];
                    hfrag[rb][4 * h + kp][0] = ep1h2(acc1[rb][lA][0], acc1[rb][lA][1], bA);
                    hfrag[rb][4 * h + kp][1] = ep1h2(acc1[rb][lA][2], acc1[rb][lA][3], bA);
                    hfrag[rb][4 * h + kp][2] = ep1h2(acc1[rb][lB][0], acc1[rb][lB][1], bB);
                    hfrag[rb][4 * h + kp][3] = ep1h2(acc1[rb][lB][2], acc1[rb][lB][3], bB);
                }
        }
        // ---- GEMM2 first ----
#pragma unroll
        for (int rb = 0; rb < 2; rb++)
#pragma unroll
            for (int i = 0; i < 8; i++)
#pragma unroll
                for (int j = 0; j < 4; j++) acc2[rb][i][j] = 0.0f;
#pragma unroll
        for (int kt = 0; kt < 8; kt++) {
            uint32_t wb = sb + OFF_W2F + wofF + ((uint32_t)(kt * 4 * 32 + lane)) * 16;
#pragma unroll
            for (int ntp = 0; ntp < 4; ntp++) {
                uint32_t q[4];
                lds128(q, wb + (uint32_t)ntp * 512);
                mma_f16(acc2[0][2 * ntp],     hfrag[0][kt], q[0], q[1]);
                mma_f16(acc2[0][2 * ntp + 1], hfrag[0][kt], q[2], q[3]);
                mma_f16(acc2[1][2 * ntp],     hfrag[1][kt], q[0], q[1]);
                mma_f16(acc2[1][2 * ntp + 1], hfrag[1][kt], q[2], q[3]);
            }
        }

        // ---- issue SECOND-tower gather pass A (latency hides under ep2) ----
        float4 stgA[8];
#pragma unroll
        for (int k = 0; k < 4; k++) {
            int idk = __shfl_sync(0xffffffffu, idS, k * 4 + rg);
            const float4* src = (const float4*)(tblS + (size_t)(uint32_t)idk * 64);
            stgA[2 * k]     = __ldg(src + gs);
            stgA[2 * k + 1] = __ldg(src + 8 + gs);
        }

        // ---- ep2 first: bias + relu + l2norm -> VEC (fp16 frag-linear) ----
        {
            const float* b2p = (const float*)(smem + OFF_B2) + b2F;
#pragma unroll
            for (int rb = 0; rb < 2; rb++) {
                float ssA = 0.0f, ssB = 0.0f;
#pragma unroll
                for (int nt = 0; nt < 8; nt++) {
                    int c0 = nt * 8 + tg * 2;
                    acc2[rb][nt][0] = fmaxf(acc2[rb][nt][0] + b2p[c0],     0.0f);
                    acc2[rb][nt][1] = fmaxf(acc2[rb][nt][1] + b2p[c0 + 1], 0.0f);
                    acc2[rb][nt][2] = fmaxf(acc2[rb][nt][2] + b2p[c0],     0.0f);
                    acc2[rb][nt][3] = fmaxf(acc2[rb][nt][3] + b2p[c0 + 1], 0.0f);
                    ssA += acc2[rb][nt][0] * acc2[rb][nt][0] + acc2[rb][nt][1] * acc2[rb][nt][1];
                    ssB += acc2[rb][nt][2] * acc2[rb][nt][2] + acc2[rb][nt][3] * acc2[rb][nt][3];
                }
                ssA += __shfl_xor_sync(0xffffffffu, ssA, 1);
                ssA += __shfl_xor_sync(0xffffffffu, ssA, 2);
                ssB += __shfl_xor_sync(0xffffffffu, ssB, 1);
                ssB += __shfl_xor_sync(0xffffffffu, ssB, 2);
                float invA = 1.0f / fmaxf(sqrtf(ssA), 1e-12f);
                float invB = 1.0f / fmaxf(sqrtf(ssB), 1e-12f);
                uint32_t base = (uint32_t)(((wid * 2 + rb) * 8) * 32 + lane) * 8u;
#pragma unroll
                for (int nt = 0; nt < 8; nt++) {
                    uint2 v = make_uint2(packh2(acc2[rb][nt][0] * invA, acc2[rb][nt][1] * invA),
                                         packh2(acc2[rb][nt][2] * invB, acc2[rb][nt][3] * invB));
                    *(uint2*)(smem + OFF_VEC + base + (uint32_t)nt * 256u) = v;
                }
            }
        }
        __syncwarp();   // all first-tower X reads done before overwrite

        // ---- convert pass A, then pass B of SECOND tower into X ----
#pragma unroll
        for (int k = 0; k < 4; k++) {
            int lrow = k * 4 + rg;
#pragma unroll
            for (int half = 0; half < 2; half++) {
                float4 v = stgA[2 * k + half];
                uint32_t chunk = (uint32_t)(half * 4 + (gs >> 1));
                uint32_t ad = (uint32_t)lrow * 128 + ((chunk ^ (uint32_t)(lrow & 7)) << 4) + (uint32_t)(gs & 1) * 8;
                *(uint2*)(smem + (xbase - sb) + ad) = make_uint2(packh2(v.x, v.y), packh2(v.z, v.w));
            }
        }
        {
            float4 stg[8];
#pragma unroll
            for (int k = 0; k < 4; k++) {
                int idk = __shfl_sync(0xffffffffu, idS, 16 + k * 4 + rg);
                const float4* src = (const float4*)(tblS + (size_t)(uint32_t)idk * 64);
                stg[2 * k]     = __ldg(src + gs);
                stg[2 * k + 1] = __ldg(src + 8 + gs);
            }
#pragma unroll
            for (int k = 0; k < 4; k++) {
                int lrow = 16 + k * 4 + rg;
#pragma unroll
                for (int half = 0; half < 2; half++) {
                    float4 v = stg[2 * k + half];
                    uint32_t chunk = (uint32_t)(half * 4 + (gs >> 1));
                    uint32_t ad = (uint32_t)lrow * 128 + ((chunk ^ (uint32_t)(lrow & 7)) << 4) + (uint32_t)(gs & 1) * 8;
                    *(uint2*)(smem + (xbase - sb) + ad) = make_uint2(packh2(v.x, v.y), packh2(v.z, v.w));
                }
            }
        }
        __syncwarp();

        // ================= SECOND tower =================
#pragma unroll
        for (int h = 0; h < 2; h++) {
            float acc1[2][8][4];
#pragma unroll
            for (int rb = 0; rb < 2; rb++)
#pragma unroll
                for (int i = 0; i < 8; i++)
#pragma unroll
                    for (int j = 0; j < 4; j++) acc1[rb][i][j] = 0.0f;
#pragma unroll
            for (int kt = 0; kt < 4; kt++) {
                uint32_t A0[4], A1[4];
                uint32_t chg = (uint32_t)(kt * 2 + khalf);
                ldm4(A0, xbase + l0b + ((chg ^ l0x) << 4));
                ldm4(A1, xbase + l1b + ((chg ^ l1x) << 4));
                uint32_t wb = sb + OFF_W1F + wofS + ((uint32_t)((kt * 8 + h * 4) * 32 + lane)) * 16;
#pragma unroll
                for (int i = 0; i < 4; i++) {
                    uint32_t q[4];
                    lds128(q, wb + (uint32_t)i * 512);
                    mma_f16(acc1[0][2 * i],     A0, q[0], q[1]);
                    mma_f16(acc1[0][2 * i + 1], A0, q[2], q[3]);
                    mma_f16(acc1[1][2 * i],     A1, q[0], q[1]);
                    mma_f16(acc1[1][2 * i + 1], A1, q[2], q[3]);
                }
            }
            const uint32_t* b1p = (const uint32_t*)(smem + OFF_B1H + b1hS);
#pragma unroll
            for (int rb = 0; rb < 2; rb++)
#pragma unroll
                for (int kp = 0; kp < 4; kp++) {
                    int lA = 2 * kp, lB = 2 * kp + 1;
                    uint32_t bA = b1p[(8 * h + lA) * 4 + tg];
                    uint32_t bB = b1p[(8 * h + lB) * 4 + tg];
                    hfrag[rb][4 * h + kp][0] = ep1h2(acc1[rb][lA][0], acc1[rb][lA][1], bA);
                    hfrag[rb][4 * h + kp][1] = ep1h2(acc1[rb][lA][2], acc1[rb][lA][3], bA);
                    hfrag[rb][4 * h + kp][2] = ep1h2(acc1[rb][lB][0], acc1[rb][lB][1], bB);
                    hfrag[rb][4 * h + kp][3] = ep1h2(acc1[rb][lB][2], acc1[rb][lB][3], bB);
                }
        }
        // ---- GEMM2 second ----
#pragma unroll
        for (int rb = 0; rb < 2; rb++)
#pragma unroll
            for (int i = 0; i < 8; i++)
#pragma unroll
                for (int j = 0; j < 4; j++) acc2[rb][i][j] = 0.0f;
#pragma unroll
        for (int kt = 0; kt < 8; kt++) {
            uint32_t wb = sb + OFF_W2F + wofS + ((uint32_t)(kt * 4 * 32 + lane)) * 16;
#pragma unroll
            for (int ntp = 0; ntp < 4; ntp++) {
                uint32_t q[4];
                lds128(q, wb + (uint32_t)ntp * 512);
                mma_f16(acc2[0][2 * ntp],     hfrag[0][kt], q[0], q[1]);
                mma_f16(acc2[0][2 * ntp + 1], hfrag[0][kt], q[2], q[3]);
                mma_f16(acc2[1][2 * ntp],     hfrag[1][kt], q[0], q[1]);
                mma_f16(acc2[1][2 * ntp + 1], hfrag[1][kt], q[2], q[3]);
            }
        }
        // ---- ep2 second: bias + relu + l2norm + dot(VEC fp16) + store ----
        {
            const float* b2p = (const float*)(smem + OFF_B2) + b2S;
#pragma unroll
            for (int rb = 0; rb < 2; rb++) {
                float ssA = 0.0f, ssB = 0.0f;
#pragma unroll
                for (int nt = 0; nt < 8; nt++) {
                    int c0 = nt * 8 + tg * 2;
                    acc2[rb][nt][0] = fmaxf(acc2[rb][nt][0] + b2p[c0],     0.0f);
                    acc2[rb][nt][1] = fmaxf(acc2[rb][nt][1] + b2p[c0 + 1], 0.0f);
                    acc2[rb][nt][2] = fmaxf(acc2[rb][nt][2] + b2p[c0],     0.0f);
                    acc2[rb][nt][3] = fmaxf(acc2[rb][nt][3] + b2p[c0 + 1], 0.0f);
                    ssA += acc2[rb][nt][0] * acc2[rb][nt][0] + acc2[rb][nt][1] * acc2[rb][nt][1];
                    ssB += acc2[rb][nt][2] * acc2[rb][nt][2] + acc2[rb][nt][3] * acc2[rb][nt][3];
                }
                ssA += __shfl_xor_sync(0xffffffffu, ssA, 1);
                ssA += __shfl_xor_sync(0xffffffffu, ssA, 2);
                ssB += __shfl_xor_sync(0xffffffffu, ssB, 1);
                ssB += __shfl_xor_sync(0xffffffffu, ssB, 2);
                float invA = 1.0f / fmaxf(sqrtf(ssA), 1e-12f);
                float invB = 1.0f / fmaxf(sqrtf(ssB), 1e-12f);
                float dA = 0.0f, dB = 0.0f;
                uint32_t base = (uint32_t)(((wid * 2 + rb) * 8) * 32 + lane) * 8u;
#pragma unroll
                for (int nt = 0; nt < 8; nt++) {
                    uint2 u = *(const uint2*)(smem + OFF_VEC + base + (uint32_t)nt * 256u);
                    float2 uA = __half22float2(*(__half2*)&u.x);
                    float2 uB = __half22float2(*(__half2*)&u.y);
                    dA += uA.x * acc2[rb][nt][0] + uA.y * acc2[rb][nt][1];
                    dB += uB.x * acc2[rb][nt][2] + uB.y * acc2[rb][nt][3];
                }
                dA *= invA;
                dB *= invB;
                dA += __shfl_xor_sync(0xffffffffu, dA, 1);
                dA += __shfl_xor_sync(0xffffffffu, dA, 2);
                dB += __shfl_xor_sync(0xffffffffu, dB, 1);
                dB += __shfl_xor_sync(0xffffffffu, dB, 2);
                if (tg == 0) {
                    int r = rowbase + rb * 16 + g;
                    out[r]     = dA;
                    out[r + 8] = dB;
                }
            }
        }
        __syncwarp();
    }
}

extern "C" void kernel_launch(void* const* d_in, const int* in_sizes, int n_in,
                              void* d_out, int out_size) {
    const int*   user_ids   = (const int*)d_in[0];
    const int*   item_ids   = (const int*)d_in[1];
    const float* user_table = (const float*)d_in[2];
    const float* item_table = (const float*)d_in[3];
    const float* uW1 = (const float*)d_in[4];
    const float* ub1 = (const float*)d_in[5];
    const float* uW2 = (const float*)d_in[6];
    const float* ub2 = (const float*)d_in[7];
    const float* iW1 = (const float*)d_in[8];
    const float* ib1 = (const float*)d_in[9];
    const float* iW2 = (const float*)d_in[10];
    const float* ib2 = (const float*)d_in[11];
    float* out = (float*)d_out;

    cudaFuncSetAttribute(twotower_kernel, cudaFuncAttributeMaxDynamicSharedMemorySize, SMEM_TOTAL);
    twotower_kernel<<<NCTAS, THREADS, SMEM_TOTAL>>>(
        user_ids, item_ids, user_table, item_table,
        uW1, ub1, uW2, ub2, iW1, ib1, iW2, ib2, out);
}

// round 15
// speedup vs baseline: 1.2169x; 1.2169x over previous
#include <cuda_runtime.h>
#include <cuda_fp16.h>
#include <cstdint>

// ============================================================================
// TwoTowerModel — 12 independent warps/CTA (3/SMSP), 32 rows/warp, fp16
// mma.sync, cp.async gather into f32 smem landing, A-frags built directly
// from f32 (no fp16 X buffer), register GEMM1->GEMM2 handoff, fp16 VEC,
// warp-parity tower stagger. (baseline sm_103 ISA)
// ============================================================================

static constexpr int BATCH   = 524288;
static constexpr int NGROUPS = BATCH / 32;     // 16384 32-row groups
static constexpr int THREADS = 384;            // 12 warps, each owns a group stream
static constexpr int NCTAS   = 148;

// ---- shared memory layout (bytes) ----
static constexpr int OFF_X    = 0;             // per-warp f32 landing [12][32][64], 96K
static constexpr int OFF_VEC  = 98304;         // first-tower normalized vec fp16, 48K
static constexpr int OFF_W1F  = 147456;        // W1 frags: [tower]*16K = 32K
static constexpr int OFF_W2F  = 180224;        // W2 frags: 32K
static constexpr int OFF_B1H  = 212992;        // half2[2][64] packed layer1 bias
static constexpr int OFF_B2   = 213504;        // float[2][64]
static constexpr int SMEM_TOTAL = 214016;

__device__ __forceinline__ uint32_t smem_u32(const void* p) {
    uint32_t a;
    asm("{ .reg .u64 t; cvta.to.shared.u64 t, %1; cvt.u32.u64 %0, t; }" : "=r"(a) : "l"(p));
    return a;
}
__device__ __forceinline__ void mma_f16(float* d, const uint32_t* a, uint32_t b0, uint32_t b1) {
    asm volatile("mma.sync.aligned.m16n8k16.row.col.f32.f16.f16.f32 "
        "{%0,%1,%2,%3}, {%4,%5,%6,%7}, {%8,%9}, {%0,%1,%2,%3};"
        : "+f"(d[0]), "+f"(d[1]), "+f"(d[2]), "+f"(d[3])
        : "r"(a[0]), "r"(a[1]), "r"(a[2]), "r"(a[3]), "r"(b0), "r"(b1));
}
__device__ __forceinline__ void lds128(uint32_t* q, uint32_t addr) {
    asm volatile("ld.shared.v4.b32 {%0,%1,%2,%3}, [%2];" // placeholder fixed below
        : "=r"(q[0]), "=r"(q[1]), "=r"(q[2]), "=r"(q[3]) : "r"(addr));
}
__device__ __forceinline__ void lds128v(uint32_t* q, uint32_t addr) {
    asm volatile("ld.shared.v4.b32 {%0,%1,%2,%3}, [%4];"
        : "=r"(q[0]), "=r"(q[1]), "=r"(q[2]), "=r"(q[3]) : "r"(addr));
}
__device__ __forceinline__ uint32_t packh2(float a, float b) {
    __half2 h = __floats2half2_rn(a, b);
    return *(uint32_t*)&h;
}
// load 2 adjacent f32 from smem, convert+pack to fp16x2
__device__ __forceinline__ uint32_t ldcvt(uint32_t addr) {
    float x, y;
    asm volatile("ld.shared.v2.f32 {%0,%1}, [%2];" : "=f"(x), "=f"(y) : "r"(addr));
    return packh2(x, y);
}
__device__ __forceinline__ uint32_t ep1h2(float a, float b, uint32_t bias2) {
    __half2 x = __floats2half2_rn(a, b);
    x = __hmax2(__hadd2(x, *(__half2*)&bias2), __half2(__float2half_rn(0.0f), __float2half_rn(0.0f)));
    return *(uint32_t*)&x;
}
#define CP_ASYNC16(dst, src) \
    asm volatile("cp.async.cg.shared.global [%0], [%1], 16;" :: "r"(dst), "l"(src) : "memory")
#define CP_COMMIT() asm volatile("cp.async.commit_group;" ::: "memory")
#define CP_WAIT0()  asm volatile("cp.async.wait_group 0;" ::: "memory")

__global__ __launch_bounds__(THREADS, 1)
void twotower_kernel(
    const int* __restrict__ user_ids, const int* __restrict__ item_ids,
    const float* __restrict__ user_table, const float* __restrict__ item_table,
    const float* __restrict__ uW1, const float* __restrict__ ub1,
    const float* __restrict__ uW2, const float* __restrict__ ub2,
    const float* __restrict__ iW1, const float* __restrict__ ib1,
    const float* __restrict__ iW2, const float* __restrict__ ib2,
    float* __restrict__ out)
{
    extern __shared__ char smem[];
    const uint32_t sb = smem_u32(smem);
    const int tid  = threadIdx.x;
    const int wid  = tid >> 5;
    const int lane = tid & 31;
    const int tg   = lane & 3;
    const int g    = lane >> 2;

    // ============ stage weights as nt-paired mma B-fragments (fp16) ====
    for (int t = 0; t < 2; t++) {
        const float* gW1 = t ? iW1 : uW1;   // [64][128] row-major
        const float* gW2 = t ? iW2 : uW2;   // [128][64]
        const float* gb1 = t ? ib1 : ub1;
        const float* gb2 = t ? ib2 : ub2;
        for (int p = tid; p < 1024; p += THREADS) {       // W1: kt(4) x ntp(8) x lane(32)
            int kt = p >> 8, ntp = (p >> 5) & 7, ln = p & 31;
            int ltg = ln & 3, lg = ln >> 2;
            int k0 = kt * 16 + ltg * 2;
            uint32_t q[4];
#pragma unroll
            for (int s = 0; s < 2; s++) {
                int n = (2 * ntp + s) * 8 + lg;
                q[2 * s + 0] = packh2(__ldg(gW1 + k0 * 128 + n),       __ldg(gW1 + (k0 + 1) * 128 + n));
                q[2 * s + 1] = packh2(__ldg(gW1 + (k0 + 8) * 128 + n), __ldg(gW1 + (k0 + 9) * 128 + n));
            }
            *((uint4*)(smem + OFF_W1F + t * 16384) + p) = make_uint4(q[0], q[1], q[2], q[3]);
        }
        for (int p = tid; p < 1024; p += THREADS) {       // W2: kt(8) x ntp(4) x lane(32)
            int kt = p >> 7, ntp = (p >> 5) & 3, ln = p & 31;
            int ltg = ln & 3, lg = ln >> 2;
            int k0 = kt * 16 + ltg * 2;
            uint32_t q[4];
#pragma unroll
            for (int s = 0; s < 2; s++) {
                int n = (2 * ntp + s) * 8 + lg;
                q[2 * s + 0] = packh2(__ldg(gW2 + k0 * 64 + n),       __ldg(gW2 + (k0 + 1) * 64 + n));
                q[2 * s + 1] = packh2(__ldg(gW2 + (k0 + 8) * 64 + n), __ldg(gW2 + (k0 + 9) * 64 + n));
            }
            *((uint4*)(smem + OFF_W2F + t * 16384) + p) = make_uint4(q[0], q[1], q[2], q[3]);
        }
        if (tid < 64) {   // packed half2 layer-1 bias: idx = nt*4+tg
            int nt = tid >> 2, ltg = tid & 3;
            int c0 = nt * 8 + ltg * 2;
            ((uint32_t*)(smem + OFF_B1H))[t * 64 + tid] = packh2(__ldg(gb1 + c0), __ldg(gb1 + c0 + 1));
        }
        if (tid < 64)  ((float*)(smem + OFF_B2))[t * 64 + tid] = __ldg(gb2 + tid);
    }
    __syncthreads();

    const int pf = wid & 1;                   // parity: which tower goes first
    const int* idsF = pf ? item_ids : user_ids;
    const int* idsS = pf ? user_ids : item_ids;
    const float* tblF = pf ? item_table : user_table;
    const float* tblS = pf ? user_table : item_table;
    const uint32_t wofF = pf ? 16384u : 0u;
    const uint32_t wofS = 16384u - wofF;
    const uint32_t b1hF = (uint32_t)pf * 256u, b1hS = 256u - b1hF;
    const int b2F = pf * 64, b2S = 64 - b2F;

    const uint32_t xb = sb + OFF_X + (uint32_t)wid * 8192u;   // warp's f32 landing
    const int rg = lane >> 3;                 // gather: row-in-group-of-4
    const int gs = lane & 7;                  // 16B sector within 128B half-row
    const uint32_t g2 = (uint32_t)(g << 1);   // A-load swizzle term (row&7 == g always)
    const uint32_t coff = (uint32_t)((tg & 1) * 8);
    const uint32_t rbase0 = (uint32_t)g * 256u;          // row g
    const uint32_t rbase1 = rbase0 + 2048u;              // row g+8
    const int gstride = (int)gridDim.x * 12;

    // ---------------- prologue: issue tile0 first-tower gather ----------------
    int gid = blockIdx.x * 12 + wid;
    {
        int idF0 = __ldg(idsF + gid * 32 + lane);
#pragma unroll
        for (int k = 0; k < 8; k++) {
            int idk = __shfl_sync(0xffffffffu, idF0, k * 4 + rg);
            const char* src = (const char*)(tblF + (size_t)(uint32_t)idk * 64);
            int row = k * 4 + rg;
#pragma unroll
            for (int half = 0; half < 2; half++) {
                uint32_t chunk = (uint32_t)(half * 8 + gs);
                uint32_t ad = (uint32_t)row * 256u + ((chunk ^ (uint32_t)((row & 7) << 1)) << 4);
                CP_ASYNC16(xb + ad, src + half * 128 + gs * 16);
            }
        }
        CP_COMMIT();
    }

    for (; gid < NGROUPS; gid += gstride) {
        const int rowbase = gid * 32;
        int gnext = gid + gstride; if (gnext >= NGROUPS) gnext = gid;
        int idS      = __ldg(idsS + rowbase + lane);
        int idF_next = __ldg(idsF + gnext * 32 + lane);

        uint32_t hfrag[2][8][4];
        float acc2[2][8][4];

        // ---- wait first-tower landing ----
        CP_WAIT0();
        __syncwarp();

        // ================= FIRST tower: GEMM1 (A from f32 landing) ==========
#pragma unroll
        for (int h = 0; h < 2; h++) {
            float acc1[2][8][4];
#pragma unroll
            for (int rb = 0; rb < 2; rb++)
#pragma unroll
                for (int i = 0; i < 8; i++)
#pragma unroll
                    for (int j = 0; j < 4; j++) acc1[rb][i][j] = 0.0f;
#pragma unroll
            for (int kt = 0; kt < 4; kt++) {
                uint32_t c0 = (uint32_t)(kt * 4 + (tg >> 1));
                uint32_t s0 = ((c0 ^ g2) << 4) + coff;
                uint32_t s2 = (((c0 + 2) ^ g2) << 4) + coff;
                uint32_t A0[4], A1[4];
                A0[0] = ldcvt(xb + rbase0 + s0);
                A0[1] = ldcvt(xb + rbase1 + s0);
                A0[2] = ldcvt(xb + rbase0 + s2);
                A0[3] = ldcvt(xb + rbase1 + s2);
                A1[0] = ldcvt(xb + 4096u + rbase0 + s0);
                A1[1] = ldcvt(xb + 4096u + rbase1 + s0);
                A1[2] = ldcvt(xb + 4096u + rbase0 + s2);
                A1[3] = ldcvt(xb + 4096u + rbase1 + s2);
                uint32_t wb = sb + OFF_W1F + wofF + ((uint32_t)((kt * 8 + h * 4) * 32 + lane)) * 16;
#pragma unroll
                for (int i = 0; i < 4; i++) {
                    uint32_t q[4];
                    lds128v(q, wb + (uint32_t)i * 512);
                    mma_f16(acc1[0][2 * i],     A0, q[0], q[1]);
                    mma_f16(acc1[0][2 * i + 1], A0, q[2], q[3]);
                    mma_f16(acc1[1][2 * i],     A1, q[0], q[1]);
                    mma_f16(acc1[1][2 * i + 1], A1, q[2], q[3]);
                }
            }
            const uint32_t* b1p = (const uint32_t*)(smem + OFF_B1H + b1hF);
#pragma unroll
            for (int rb = 0; rb < 2; rb++)
#pragma unroll
                for (int kp = 0; kp < 4; kp++) {
                    int lA = 2 * kp, lB = 2 * kp + 1;
                    uint32_t bA = b1p[(8 * h + lA) * 4 + tg];
                    uint32_t bB = b1p[(8 * h + lB) * 4 + tg];
                    hfrag[rb][4 * h + kp][0] = ep1h2(acc1[rb][lA][0], acc1[rb][lA][1], bA);
                    hfrag[rb][4 * h + kp][1] = ep1h2(acc1[rb][lA][2], acc1[rb][lA][3], bA);
                    hfrag[rb][4 * h + kp][2] = ep1h2(acc1[rb][lB][0], acc1[rb][lB][1], bB);
                    hfrag[rb][4 * h + kp][3] = ep1h2(acc1[rb][lB][2], acc1[rb][lB][3], bB);
                }
        }

        // ---- issue SECOND-tower gather (landing reads complete) ----
        __syncwarp();
#pragma unroll
        for (int k = 0; k < 8; k++) {
            int idk = __shfl_sync(0xffffffffu, idS, k * 4 + rg);
            const char* src = (const char*)(tblS + (size_t)(uint32_t)idk * 64);
            int row = k * 4 + rg;
#pragma unroll
            for (int half = 0; half < 2; half++) {
                uint32_t chunk = (uint32_t)(half * 8 + gs);
                uint32_t ad = (uint32_t)row * 256u + ((chunk ^ (uint32_t)((row & 7) << 1)) << 4);
                CP_ASYNC16(xb + ad, src + half * 128 + gs * 16);
            }
        }
        CP_COMMIT();

        // ---- GEMM2 first ----
#pragma unroll
        for (int rb = 0; rb < 2; rb++)
#pragma unroll
            for (int i = 0; i < 8; i++)
#pragma unroll
                for (int j = 0; j < 4; j++) acc2[rb][i][j] = 0.0f;
#pragma unroll
        for (int kt = 0; kt < 8; kt++) {
            uint32_t wb = sb + OFF_W2F + wofF + ((uint32_t)(kt * 4 * 32 + lane)) * 16;
#pragma unroll
            for (int ntp = 0; ntp < 4; ntp++) {
                uint32_t q[4];
                lds128v(q, wb + (uint32_t)ntp * 512);
                mma_f16(acc2[0][2 * ntp],     hfrag[0][kt], q[0], q[1]);
                mma_f16(acc2[0][2 * ntp + 1], hfrag[0][kt], q[2], q[3]);
                mma_f16(acc2[1][2 * ntp],     hfrag[1][kt], q[0], q[1]);
                mma_f16(acc2[1][2 * ntp + 1], hfrag[1][kt], q[2], q[3]);
            }
        }
        // ---- ep2 first: bias + relu + l2norm -> VEC (fp16, per-lane slots) ----
        {
            const float* b2p = (const float*)(smem + OFF_B2) + b2F;
#pragma unroll
            for (int rb = 0; rb < 2; rb++) {
                float ssA = 0.0f, ssB = 0.0f;
#pragma unroll
                for (int nt = 0; nt < 8; nt++) {
                    int c0 = nt * 8 + tg * 2;
                    acc2[rb][nt][0] = fmaxf(acc2[rb][nt][0] + b2p[c0],     0.0f);
                    acc2[rb][nt][1] = fmaxf(acc2[rb][nt][1] + b2p[c0 + 1], 0.0f);
                    acc2[rb][nt][2] = fmaxf(acc2[rb][nt][2] + b2p[c0],     0.0f);
                    acc2[rb][nt][3] = fmaxf(acc2[rb][nt][3] + b2p[c0 + 1], 0.0f);
                    ssA += acc2[rb][nt][0] * acc2[rb][nt][0] + acc2[rb][nt][1] * acc2[rb][nt][1];
                    ssB += acc2[rb][nt][2] * acc2[rb][nt][2] + acc2[rb][nt][3] * acc2[rb][nt][3];
                }
                ssA += __shfl_xor_sync(0xffffffffu, ssA, 1);
                ssA += __shfl_xor_sync(0xffffffffu, ssA, 2);
                ssB += __shfl_xor_sync(0xffffffffu, ssB, 1);
                ssB += __shfl_xor_sync(0xffffffffu, ssB, 2);
                float invA = 1.0f / fmaxf(sqrtf(ssA), 1e-12f);
                float invB = 1.0f / fmaxf(sqrtf(ssB), 1e-12f);
                uint32_t base = (uint32_t)(((wid * 2 + rb) * 8) * 32 + lane) * 8u;
#pragma unroll
                for (int nt = 0; nt < 8; nt++) {
                    uint2 v = make_uint2(packh2(acc2[rb][nt][0] * invA, acc2[rb][nt][1] * invA),
                                         packh2(acc2[rb][nt][2] * invB, acc2[rb][nt][3] * invB));
                    *(uint2*)(smem + OFF_VEC + base + (uint32_t)nt * 256u) = v;
                }
            }
        }

        // ---- wait second-tower landing ----
        CP_WAIT0();
        __syncwarp();

        // ================= SECOND tower: GEMM1 =================
#pragma unroll
        for (int h = 0; h < 2; h++) {
            float acc1[2][8][4];
#pragma unroll
            for (int rb = 0; rb < 2; rb++)
#pragma unroll
                for (int i = 0; i < 8; i++)
#pragma unroll
                    for (int j = 0; j < 4; j++) acc1[rb][i][j] = 0.0f;
#pragma unroll
            for (int kt = 0; kt < 4; kt++) {
                uint32_t c0 = (uint32_t)(kt * 4 + (tg >> 1));
                uint32_t s0 = ((c0 ^ g2) << 4) + coff;
                uint32_t s2 = (((c0 + 2) ^ g2) << 4) + coff;
                uint32_t A0[4], A1[4];
                A0[0] = ldcvt(xb + rbase0 + s0);
                A0[1] = ldcvt(xb + rbase1 + s0);
                A0[2] = ldcvt(xb + rbase0 + s2);
                A0[3] = ldcvt(xb + rbase1 + s2);
                A1[0] = ldcvt(xb + 4096u + rbase0 + s0);
                A1[1] = ldcvt(xb + 4096u + rbase1 + s0);
                A1[2] = ldcvt(xb + 4096u + rbase0 + s2);
                A1[3] = ldcvt(xb + 4096u + rbase1 + s2);
                uint32_t wb = sb + OFF_W1F + wofS + ((uint32_t)((kt * 8 + h * 4) * 32 + lane)) * 16;
#pragma unroll
                for (int i = 0; i < 4; i++) {
                    uint32_t q[4];
                    lds128v(q, wb + (uint32_t)i * 512);
                    mma_f16(acc1[0][2 * i],     A0, q[0], q[1]);
                    mma_f16(acc1[0][2 * i + 1], A0, q[2], q[3]);
                    mma_f16(acc1[1][2 * i],     A1, q[0], q[1]);
                    mma_f16(acc1[1][2 * i + 1], A1, q[2], q[3]);
                }
            }
            const uint32_t* b1p = (const uint32_t*)(smem + OFF_B1H + b1hS);
#pragma unroll
            for (int rb = 0; rb < 2; rb++)
#pragma unroll
                for (int kp = 0; kp < 4; kp++) {
                    int lA = 2 * kp, lB = 2 * kp + 1;
                    uint32_t bA = b1p[(8 * h + lA) * 4 + tg];
                    uint32_t bB = b1p[(8 * h + lB) * 4 + tg];
                    hfrag[rb][4 * h + kp][0] = ep1h2(acc1[rb][lA][0], acc1[rb][lA][1], bA);
                    hfrag[rb][4 * h + kp][1] = ep1h2(acc1[rb][lA][2], acc1[rb][lA][3], bA);
                    hfrag[rb][4 * h + kp][2] = ep1h2(acc1[rb][lB][0], acc1[rb][lB][1], bB);
                    hfrag[rb][4 * h + kp][3] = ep1h2(acc1[rb][lB][2], acc1[rb][lB][3], bB);
                }
        }

        // ---- issue NEXT-tile first-tower gather ----
        __syncwarp();
#pragma unroll
        for (int k = 0; k < 8; k++) {
            int idk = __shfl_sync(0xffffffffu, idF_next, k * 4 + rg);
            const char* src = (const char*)(tblF + (size_t)(uint32_t)idk * 64);
            int row = k * 4 + rg;
#pragma unroll
            for (int half = 0; half < 2; half++) {
                uint32_t chunk = (uint32_t)(half * 8 + gs);
                uint32_t ad = (uint32_t)row * 256u + ((chunk ^ (uint32_t)((row & 7) << 1)) << 4);
                CP_ASYNC16(xb + ad, src + half * 128 + gs * 16);
            }
        }
        CP_COMMIT();

        // ---- GEMM2 second ----
#pragma unroll
        for (int rb = 0; rb < 2; rb++)
#pragma unroll
            for (int i = 0; i < 8; i++)
#pragma unroll
                for (int j = 0; j < 4; j++) acc2[rb][i][j] = 0.0f;
#pragma unroll
        for (int kt = 0; kt < 8; kt++) {
            uint32_t wb = sb + OFF_W2F + wofS + ((uint32_t)(kt * 4 * 32 + lane)) * 16;
#pragma unroll
            for (int ntp = 0; ntp < 4; ntp++) {
                uint32_t q[4];
                lds128v(q, wb + (uint32_t)ntp * 512);
                mma_f16(acc2[0][2 * ntp],     hfrag[0][kt], q[0], q[1]);
                mma_f16(acc2[0][2 * ntp + 1], hfrag[0][kt], q[2], q[3]);
                mma_f16(acc2[1][2 * ntp],     hfrag[1][kt], q[0], q[1]);
                mma_f16(acc2[1][2 * ntp + 1], hfrag[1][kt], q[2], q[3]);
            }
        }
        // ---- ep2 second: bias + relu + l2norm + dot(VEC fp16) + store ----
        {
            const float* b2p = (const float*)(smem + OFF_B2) + b2S;
#pragma unroll
            for (int rb = 0; rb < 2; rb++) {
                float ssA = 0.0f, ssB = 0.0f;
#pragma unroll
                for (int nt = 0; nt < 8; nt++) {
                    int c0 = nt * 8 + tg * 2;
                    acc2[rb][nt][0] = fmaxf(acc2[rb][nt][0] + b2p[c0],     0.0f);
                    acc2[rb][nt][1] = fmaxf(acc2[rb][nt][1] + b2p[c0 + 1], 0.0f);
                    acc2[rb][nt][2] = fmaxf(acc2[rb][nt][2] + b2p[c0],     0.0f);
                    acc2[rb][nt][3] = fmaxf(acc2[rb][nt][3] + b2p[c0 + 1], 0.0f);
                    ssA += acc2[rb][nt][0] * acc2[rb][nt][0] + acc2[rb][nt][1] * acc2[rb][nt][1];
                    ssB += acc2[rb][nt][2] * acc2[rb][nt][2] + acc2[rb][nt][3] * acc2[rb][nt][3];
                }
                ssA += __shfl_xor_sync(0xffffffffu, ssA, 1);
                ssA += __shfl_xor_sync(0xffffffffu, ssA, 2);
                ssB += __shfl_xor_sync(0xffffffffu, ssB, 1);
                ssB += __shfl_xor_sync(0xffffffffu, ssB, 2);
                float invA = 1.0f / fmaxf(sqrtf(ssA), 1e-12f);
                float invB = 1.0f / fmaxf(sqrtf(ssB), 1e-12f);
                float dA = 0.0f, dB = 0.0f;
                uint32_t base = (uint32_t)(((wid * 2 + rb) * 8) * 32 + lane) * 8u;
#pragma unroll
                for (int nt = 0; nt < 8; nt++) {
                    uint2 u = *(const uint2*)(smem + OFF_VEC + base + (uint32_t)nt * 256u);
                    float2 uA = __half22float2(*(__half2*)&u.x);
                    float2 uB = __half22float2(*(__half2*)&u.y);
                    dA += uA.x * acc2[rb][nt][0] + uA.y * acc2[rb][nt][1];
                    dB += uB.x * acc2[rb][nt][2] + uB.y * acc2[rb][nt][3];
                }
                dA *= invA;
                dB *= invB;
                dA += __shfl_xor_sync(0xffffffffu, dA, 1);
                dA += __shfl_xor_sync(0xffffffffu, dA, 2);
                dB += __shfl_xor_sync(0xffffffffu, dB, 1);
                dB += __shfl_xor_sync(0xffffffffu, dB, 2);
                if (tg == 0) {
                    int r = rowbase + rb * 16 + g;
                    out[r]     = dA;
                    out[r + 8] = dB;
                }
            }
        }
        __syncwarp();
    }
}

extern "C" void kernel_launch(void* const* d_in, const int* in_sizes, int n_in,
                              void* d_out, int out_size) {
    const int*   user_ids   = (const int*)d_in[0];
    const int*   item_ids   = (const int*)d_in[1];
    const float* user_table = (const float*)d_in[2];
    const float* item_table = (const float*)d_in[3];
    const float* uW1 = (const float*)d_in[4];
    const float* ub1 = (const float*)d_in[5];
    const float* uW2 = (const float*)d_in[6];
    const float* ub2 = (const float*)d_in[7];
    const float* iW1 = (const float*)d_in[8];
    const float* ib1 = (const float*)d_in[9];
    const float* iW2 = (const float*)d_in[10];
    const float* ib2 = (const float*)d_in[11];
    float* out = (float*)d_out;

    cudaFuncSetAttribute(twotower_kernel, cudaFuncAttributeMaxDynamicSharedMemorySize, SMEM_TOTAL);
    twotower_kernel<<<NCTAS, THREADS, SMEM_TOTAL>>>(
        user_ids, item_ids, user_table, item_table,
        uW1, ub1, uW2, ub2, iW1, ib1, iW2, ib2, out);
}

// round 16
// speedup vs baseline: 1.2188x; 1.0016x over previous
#include <cuda_runtime.h>
#include <cuda_fp16.h>
#include <cstdint>

// ============================================================================
// TwoTowerModel — 12 independent warps/CTA (3/SMSP), 32 rows/warp, fp16
// mma.sync, cp.async gather into f32 smem landing, A-frags built once per
// tower into registers (Afr), register GEMM1->GEMM2 handoff, fp16 VEC,
// warp-parity tower stagger. (baseline sm_103 ISA)
// ============================================================================

static constexpr int BATCH   = 524288;
static constexpr int NGROUPS = BATCH / 32;     // 16384 32-row groups
static constexpr int THREADS = 384;            // 12 warps, each owns a group stream
static constexpr int NCTAS   = 148;

// ---- shared memory layout (bytes) ----
static constexpr int OFF_X    = 0;             // per-warp f32 landing [12][32][64], 96K
static constexpr int OFF_VEC  = 98304;         // first-tower normalized vec fp16, 48K
static constexpr int OFF_W1F  = 147456;        // W1 frags: [tower]*16K = 32K
static constexpr int OFF_W2F  = 180224;        // W2 frags: 32K
static constexpr int OFF_B1H  = 212992;        // half2[2][64] packed layer1 bias
static constexpr int OFF_B2   = 213504;        // float[2][64]
static constexpr int SMEM_TOTAL = 214016;

__device__ __forceinline__ uint32_t smem_u32(const void* p) {
    uint32_t a;
    asm("{ .reg .u64 t; cvta.to.shared.u64 t, %1; cvt.u32.u64 %0, t; }" : "=r"(a) : "l"(p));
    return a;
}
__device__ __forceinline__ void mma_f16(float* d, const uint32_t* a, uint32_t b0, uint32_t b1) {
    asm volatile("mma.sync.aligned.m16n8k16.row.col.f32.f16.f16.f32 "
        "{%0,%1,%2,%3}, {%4,%5,%6,%7}, {%8,%9}, {%0,%1,%2,%3};"
        : "+f"(d[0]), "+f"(d[1]), "+f"(d[2]), "+f"(d[3])
        : "r"(a[0]), "r"(a[1]), "r"(a[2]), "r"(a[3]), "r"(b0), "r"(b1));
}
__device__ __forceinline__ void lds128v(uint32_t* q, uint32_t addr) {
    asm volatile("ld.shared.v4.b32 {%0,%1,%2,%3}, [%4];"
        : "=r"(q[0]), "=r"(q[1]), "=r"(q[2]), "=r"(q[3]) : "r"(addr));
}
__device__ __forceinline__ uint32_t packh2(float a, float b) {
    __half2 h = __floats2half2_rn(a, b);
    return *(uint32_t*)&h;
}
// load 2 adjacent f32 from smem, convert+pack to fp16x2
__device__ __forceinline__ uint32_t ldcvt(uint32_t addr) {
    float x, y;
    asm volatile("ld.shared.v2.f32 {%0,%1}, [%2];" : "=f"(x), "=f"(y) : "r"(addr));
    return packh2(x, y);
}
__device__ __forceinline__ uint32_t ep1h2(float a, float b, uint32_t bias2) {
    __half2 x = __floats2half2_rn(a, b);
    x = __hmax2(__hadd2(x, *(__half2*)&bias2), __half2(__float2half_rn(0.0f), __float2half_rn(0.0f)));
    return *(uint32_t*)&x;
}
#define CP_ASYNC16(dst, src) \
    asm volatile("cp.async.cg.shared.global [%0], [%1], 16;" :: "r"(dst), "l"(src) : "memory")
#define CP_COMMIT() asm volatile("cp.async.commit_group;" ::: "memory")
#define CP_WAIT0()  asm volatile("cp.async.wait_group 0;" ::: "memory")

__global__ __launch_bounds__(THREADS, 1)
void twotower_kernel(
    const int* __restrict__ user_ids, const int* __restrict__ item_ids,
    const float* __restrict__ user_table, const float* __restrict__ item_table,
    const float* __restrict__ uW1, const float* __restrict__ ub1,
    const float* __restrict__ uW2, const float* __restrict__ ub2,
    const float* __restrict__ iW1, const float* __restrict__ ib1,
    const float* __restrict__ iW2, const float* __restrict__ ib2,
    float* __restrict__ out)
{
    extern __shared__ char smem[];
    const uint32_t sb = smem_u32(smem);
    const int tid  = threadIdx.x;
    const int wid  = tid >> 5;
    const int lane = tid & 31;
    const int tg   = lane & 3;
    const int g    = lane >> 2;

    // ============ stage weights as nt-paired mma B-fragments (fp16) ====
    for (int t = 0; t < 2; t++) {
        const float* gW1 = t ? iW1 : uW1;   // [64][128] row-major
        const float* gW2 = t ? iW2 : uW2;   // [128][64]
        const float* gb1 = t ? ib1 : ub1;
        const float* gb2 = t ? ib2 : ub2;
        for (int p = tid; p < 1024; p += THREADS) {       // W1: kt(4) x ntp(8) x lane(32)
            int kt = p >> 8, ntp = (p >> 5) & 7, ln = p & 31;
            int ltg = ln & 3, lg = ln >> 2;
            int k0 = kt * 16 + ltg * 2;
            uint32_t q[4];
#pragma unroll
            for (int s = 0; s < 2; s++) {
                int n = (2 * ntp + s) * 8 + lg;
                q[2 * s + 0] = packh2(__ldg(gW1 + k0 * 128 + n),       __ldg(gW1 + (k0 + 1) * 128 + n));
                q[2 * s + 1] = packh2(__ldg(gW1 + (k0 + 8) * 128 + n), __ldg(gW1 + (k0 + 9) * 128 + n));
            }
            *((uint4*)(smem + OFF_W1F + t * 16384) + p) = make_uint4(q[0], q[1], q[2], q[3]);
        }
        for (int p = tid; p < 1024; p += THREADS) {       // W2: kt(8) x ntp(4) x lane(32)
            int kt = p >> 7, ntp = (p >> 5) & 3, ln = p & 31;
            int ltg = ln & 3, lg = ln >> 2;
            int k0 = kt * 16 + ltg * 2;
            uint32_t q[4];
#pragma unroll
            for (int s = 0; s < 2; s++) {
                int n = (2 * ntp + s) * 8 + lg;
                q[2 * s + 0] = packh2(__ldg(gW2 + k0 * 64 + n),       __ldg(gW2 + (k0 + 1) * 64 + n));
                q[2 * s + 1] = packh2(__ldg(gW2 + (k0 + 8) * 64 + n), __ldg(gW2 + (k0 + 9) * 64 + n));
            }
            *((uint4*)(smem + OFF_W2F + t * 16384) + p) = make_uint4(q[0], q[1], q[2], q[3]);
        }
        if (tid < 64) {   // packed half2 layer-1 bias: idx = nt*4+tg
            int nt = tid >> 2, ltg = tid & 3;
            int c0 = nt * 8 + ltg * 2;
            ((uint32_t*)(smem + OFF_B1H))[t * 64 + tid] = packh2(__ldg(gb1 + c0), __ldg(gb1 + c0 + 1));
        }
        if (tid < 64)  ((float*)(smem + OFF_B2))[t * 64 + tid] = __ldg(gb2 + tid);
    }
    __syncthreads();

    const int pf = wid & 1;                   // parity: which tower goes first
    const int* idsF = pf ? item_ids : user_ids;
    const int* idsS = pf ? user_ids : item_ids;
    const float* tblF = pf ? item_table : user_table;
    const float* tblS = pf ? user_table : item_table;
    const uint32_t wofF = pf ? 16384u : 0u;
    const uint32_t wofS = 16384u - wofF;
    const uint32_t b1hF = (uint32_t)pf * 256u, b1hS = 256u - b1hF;
    const int b2F = pf * 64, b2S = 64 - b2F;

    const uint32_t xb = sb + OFF_X + (uint32_t)wid * 8192u;   // warp's f32 landing
    const int rg = lane >> 3;                 // gather: row-in-group-of-4
    const int gs = lane & 7;                  // 16B sector within 128B half-row
    const uint32_t g2 = (uint32_t)(g << 1);   // A-load swizzle term
    const uint32_t coff = (uint32_t)((tg & 1) * 8);
    const uint32_t rbase0 = (uint32_t)g * 256u;          // row g
    const uint32_t rbase1 = rbase0 + 2048u;              // row g+8
    const int gstride = (int)gridDim.x * 12;

    // ---------------- prologue: issue tile0 first-tower gather ----------------
    int gid = blockIdx.x * 12 + wid;
    {
        int idF0 = __ldg(idsF + gid * 32 + lane);
#pragma unroll
        for (int k = 0; k < 8; k++) {
            int idk = __shfl_sync(0xffffffffu, idF0, k * 4 + rg);
            const char* src = (const char*)(tblF + (size_t)(uint32_t)idk * 64);
            int row = k * 4 + rg;
#pragma unroll
            for (int half = 0; half < 2; half++) {
                uint32_t chunk = (uint32_t)(half * 8 + gs);
                uint32_t ad = (uint32_t)row * 256u + ((chunk ^ (uint32_t)((row & 7) << 1)) << 4);
                CP_ASYNC16(xb + ad, src + half * 128 + gs * 16);
            }
        }
        CP_COMMIT();
    }

    for (; gid < NGROUPS; gid += gstride) {
        const int rowbase = gid * 32;
        int gnext = gid + gstride; if (gnext >= NGROUPS) gnext = gid;
        int idS      = __ldg(idsS + rowbase + lane);
        int idF_next = __ldg(idsF + gnext * 32 + lane);

        uint32_t hfrag[2][8][4];
        float acc2[2][8][4];

        // ---- wait first-tower landing ----
        CP_WAIT0();
        __syncwarp();

        // ================= FIRST tower =================
        // ---- build A-frags ONCE into registers (kt x {A0,A1}) ----
        uint32_t Afr[4][8];
#pragma unroll
        for (int kt = 0; kt < 4; kt++) {
            uint32_t c0 = (uint32_t)(kt * 4 + (tg >> 1));
            uint32_t s0 = ((c0 ^ g2) << 4) + coff;
            uint32_t s2 = (((c0 + 2) ^ g2) << 4) + coff;
            Afr[kt][0] = ldcvt(xb + rbase0 + s0);
            Afr[kt][1] = ldcvt(xb + rbase1 + s0);
            Afr[kt][2] = ldcvt(xb + rbase0 + s2);
            Afr[kt][3] = ldcvt(xb + rbase1 + s2);
            Afr[kt][4] = ldcvt(xb + 4096u + rbase0 + s0);
            Afr[kt][5] = ldcvt(xb + 4096u + rbase1 + s0);
            Afr[kt][6] = ldcvt(xb + 4096u + rbase0 + s2);
            Afr[kt][7] = ldcvt(xb + 4096u + rbase1 + s2);
        }
        // ---- issue SECOND-tower gather (landing reads complete) ----
        __syncwarp();
#pragma unroll
        for (int k = 0; k < 8; k++) {
            int idk = __shfl_sync(0xffffffffu, idS, k * 4 + rg);
            const char* src = (const char*)(tblS + (size_t)(uint32_t)idk * 64);
            int row = k * 4 + rg;
#pragma unroll
            for (int half = 0; half < 2; half++) {
                uint32_t chunk = (uint32_t)(half * 8 + gs);
                uint32_t ad = (uint32_t)row * 256u + ((chunk ^ (uint32_t)((row & 7) << 1)) << 4);
                CP_ASYNC16(xb + ad, src + half * 128 + gs * 16);
            }
        }
        CP_COMMIT();

        // ---- GEMM1 first (A from Afr, reused across both h halves) ----
#pragma unroll
        for (int h = 0; h < 2; h++) {
            float acc1[2][8][4];
#pragma unroll
            for (int rb = 0; rb < 2; rb++)
#pragma unroll
                for (int i = 0; i < 8; i++)
#pragma unroll
                    for (int j = 0; j < 4; j++) acc1[rb][i][j] = 0.0f;
#pragma unroll
            for (int kt = 0; kt < 4; kt++) {
                uint32_t wb = sb + OFF_W1F + wofF + ((uint32_t)((kt * 8 + h * 4) * 32 + lane)) * 16;
#pragma unroll
                for (int i = 0; i < 4; i++) {
                    uint32_t q[4];
                    lds128v(q, wb + (uint32_t)i * 512);
                    mma_f16(acc1[0][2 * i],     Afr[kt],     q[0], q[1]);
                    mma_f16(acc1[0][2 * i + 1], Afr[kt],     q[2], q[3]);
                    mma_f16(acc1[1][2 * i],     Afr[kt] + 4, q[0], q[1]);
                    mma_f16(acc1[1][2 * i + 1], Afr[kt] + 4, q[2], q[3]);
                }
            }
            const uint32_t* b1p = (const uint32_t*)(smem + OFF_B1H + b1hF);
#pragma unroll
            for (int rb = 0; rb < 2; rb++)
#pragma unroll
                for (int kp = 0; kp < 4; kp++) {
                    int lA = 2 * kp, lB = 2 * kp + 1;
                    uint32_t bA = b1p[(8 * h + lA) * 4 + tg];
                    uint32_t bB = b1p[(8 * h + lB) * 4 + tg];
                    hfrag[rb][4 * h + kp][0] = ep1h2(acc1[rb][lA][0], acc1[rb][lA][1], bA);
                    hfrag[rb][4 * h + kp][1] = ep1h2(acc1[rb][lA][2], acc1[rb][lA][3], bA);
                    hfrag[rb][4 * h + kp][2] = ep1h2(acc1[rb][lB][0], acc1[rb][lB][1], bB);
                    hfrag[rb][4 * h + kp][3] = ep1h2(acc1[rb][lB][2], acc1[rb][lB][3], bB);
                }
        }

        // ---- GEMM2 first ----
#pragma unroll
        for (int rb = 0; rb < 2; rb++)
#pragma unroll
            for (int i = 0; i < 8; i++)
#pragma unroll
                for (int j = 0; j < 4; j++) acc2[rb][i][j] = 0.0f;
#pragma unroll
        for (int kt = 0; kt < 8; kt++) {
            uint32_t wb = sb + OFF_W2F + wofF + ((uint32_t)(kt * 4 * 32 + lane)) * 16;
#pragma unroll
            for (int ntp = 0; ntp < 4; ntp++) {
                uint32_t q[4];
                lds128v(q, wb + (uint32_t)ntp * 512);
                mma_f16(acc2[0][2 * ntp],     hfrag[0][kt], q[0], q[1]);
                mma_f16(acc2[0][2 * ntp + 1], hfrag[0][kt], q[2], q[3]);
                mma_f16(acc2[1][2 * ntp],     hfrag[1][kt], q[0], q[1]);
                mma_f16(acc2[1][2 * ntp + 1], hfrag[1][kt], q[2], q[3]);
            }
        }
        // ---- ep2 first: bias + relu + l2norm -> VEC (fp16, per-lane slots) ----
        {
            const float* b2p = (const float*)(smem + OFF_B2) + b2F;
#pragma unroll
            for (int rb = 0; rb < 2; rb++) {
                float ssA = 0.0f, ssB = 0.0f;
#pragma unroll
                for (int nt = 0; nt < 8; nt++) {
                    int c0 = nt * 8 + tg * 2;
                    acc2[rb][nt][0] = fmaxf(acc2[rb][nt][0] + b2p[c0],     0.0f);
                    acc2[rb][nt][1] = fmaxf(acc2[rb][nt][1] + b2p[c0 + 1], 0.0f);
                    acc2[rb][nt][2] = fmaxf(acc2[rb][nt][2] + b2p[c0],     0.0f);
                    acc2[rb][nt][3] = fmaxf(acc2[rb][nt][3] + b2p[c0 + 1], 0.0f);
                    ssA += acc2[rb][nt][0] * acc2[rb][nt][0] + acc2[rb][nt][1] * acc2[rb][nt][1];
                    ssB += acc2[rb][nt][2] * acc2[rb][nt][2] + acc2[rb][nt][3] * acc2[rb][nt][3];
                }
                ssA += __shfl_xor_sync(0xffffffffu, ssA, 1);
                ssA += __shfl_xor_sync(0xffffffffu, ssA, 2);
                ssB += __shfl_xor_sync(0xffffffffu, ssB, 1);
                ssB += __shfl_xor_sync(0xffffffffu, ssB, 2);
                float invA = 1.0f / fmaxf(sqrtf(ssA), 1e-12f);
                float invB = 1.0f / fmaxf(sqrtf(ssB), 1e-12f);
                uint32_t base = (uint32_t)(((wid * 2 + rb) * 8) * 32 + lane) * 8u;
#pragma unroll
                for (int nt = 0; nt < 8; nt++) {
                    uint2 v = make_uint2(packh2(acc2[rb][nt][0] * invA, acc2[rb][nt][1] * invA),
                                         packh2(acc2[rb][nt][2] * invB, acc2[rb][nt][3] * invB));
                    *(uint2*)(smem + OFF_VEC + base + (uint32_t)nt * 256u) = v;
                }
            }
        }

        // ---- wait second-tower landing ----
        CP_WAIT0();
        __syncwarp();

        // ================= SECOND tower =================
        // ---- build A-frags once ----
#pragma unroll
        for (int kt = 0; kt < 4; kt++) {
            uint32_t c0 = (uint32_t)(kt * 4 + (tg >> 1));
            uint32_t s0 = ((c0 ^ g2) << 4) + coff;
            uint32_t s2 = (((c0 + 2) ^ g2) << 4) + coff;
            Afr[kt][0] = ldcvt(xb + rbase0 + s0);
            Afr[kt][1] = ldcvt(xb + rbase1 + s0);
            Afr[kt][2] = ldcvt(xb + rbase0 + s2);
            Afr[kt][3] = ldcvt(xb + rbase1 + s2);
            Afr[kt][4] = ldcvt(xb + 4096u + rbase0 + s0);
            Afr[kt][5] = ldcvt(xb + 4096u + rbase1 + s0);
            Afr[kt][6] = ldcvt(xb + 4096u + rbase0 + s2);
            Afr[kt][7] = ldcvt(xb + 4096u + rbase1 + s2);
        }
        // ---- issue NEXT-tile first-tower gather ----
        __syncwarp();
#pragma unroll
        for (int k = 0; k < 8; k++) {
            int idk = __shfl_sync(0xffffffffu, idF_next, k * 4 + rg);
            const char* src = (const char*)(tblF + (size_t)(uint32_t)idk * 64);
            int row = k * 4 + rg;
#pragma unroll
            for (int half = 0; half < 2; half++) {
                uint32_t chunk = (uint32_t)(half * 8 + gs);
                uint32_t ad = (uint32_t)row * 256u + ((chunk ^ (uint32_t)((row & 7) << 1)) << 4);
                CP_ASYNC16(xb + ad, src + half * 128 + gs * 16);
            }
        }
        CP_COMMIT();

        // ---- GEMM1 second ----
#pragma unroll
        for (int h = 0; h < 2; h++) {
            float acc1[2][8][4];
#pragma unroll
            for (int rb = 0; rb < 2; rb++)
#pragma unroll
                for (int i = 0; i < 8; i++)
#pragma unroll
                    for (int j = 0; j < 4; j++) acc1[rb][i][j] = 0.0f;
#pragma unroll
            for (int kt = 0; kt < 4; kt++) {
                uint32_t wb = sb + OFF_W1F + wofS + ((uint32_t)((kt * 8 + h * 4) * 32 + lane)) * 16;
#pragma unroll
                for (int i = 0; i < 4; i++) {
                    uint32_t q[4];
                    lds128v(q, wb + (uint32_t)i * 512);
                    mma_f16(acc1[0][2 * i],     Afr[kt],     q[0], q[1]);
                    mma_f16(acc1[0][2 * i + 1], Afr[kt],     q[2], q[3]);
                    mma_f16(acc1[1][2 * i],     Afr[kt] + 4, q[0], q[1]);
                    mma_f16(acc1[1][2 * i + 1], Afr[kt] + 4, q[2], q[3]);
                }
            }
            const uint32_t* b1p = (const uint32_t*)(smem + OFF_B1H + b1hS);
#pragma unroll
            for (int rb = 0; rb < 2; rb++)
#pragma unroll
                for (int kp = 0; kp < 4; kp++) {
                    int lA = 2 * kp, lB = 2 * kp + 1;
                    uint32_t bA = b1p[(8 * h + lA) * 4 + tg];
                    uint32_t bB = b1p[(8 * h + lB) * 4 + tg];
                    hfrag[rb][4 * h + kp][0] = ep1h2(acc1[rb][lA][0], acc1[rb][lA][1], bA);
                    hfrag[rb][4 * h + kp][1] = ep1h2(acc1[rb][lA][2], acc1[rb][lA][3], bA);
                    hfrag[rb][4 * h + kp][2] = ep1h2(acc1[rb][lB][0], acc1[rb][lB][1], bB);
                    hfrag[rb][4 * h + kp][3] = ep1h2(acc1[rb][lB][2], acc1[rb][lB][3], bB);
                }
        }

        // ---- GEMM2 second ----
#pragma unroll
        for (int rb = 0; rb < 2; rb++)
#pragma unroll
            for (int i = 0; i < 8; i++)
#pragma unroll
                for (int j = 0; j < 4; j++) acc2[rb][i][j] = 0.0f;
#pragma unroll
        for (int kt = 0; kt < 8; kt++) {
            uint32_t wb = sb + OFF_W2F + wofS + ((uint32_t)(kt * 4 * 32 + lane)) * 16;
#pragma unroll
            for (int ntp = 0; ntp < 4; ntp++) {
                uint32_t q[4];
                lds128v(q, wb + (uint32_t)ntp * 512);
                mma_f16(acc2[0][2 * ntp],     hfrag[0][kt], q[0], q[1]);
                mma_f16(acc2[0][2 * ntp + 1], hfrag[0][kt], q[2], q[3]);
                mma_f16(acc2[1][2 * ntp],     hfrag[1][kt], q[0], q[1]);
                mma_f16(acc2[1][2 * ntp + 1], hfrag[1][kt], q[2], q[3]);
            }
        }
        // ---- ep2 second: bias + relu + l2norm + dot(VEC fp16) + store ----
        {
            const float* b2p = (const float*)(smem + OFF_B2) + b2S;
#pragma unroll
            for (int rb = 0; rb < 2; rb++) {
                float ssA = 0.0f, ssB = 0.0f;
#pragma unroll
                for (int nt = 0; nt < 8; nt++) {
                    int c0 = nt * 8 + tg * 2;
                    acc2[rb][nt][0] = fmaxf(acc2[rb][nt][0] + b2p[c0],     0.0f);
                    acc2[rb][nt][1] = fmaxf(acc2[rb][nt][1] + b2p[c0 + 1], 0.0f);
                    acc2[rb][nt][2] = fmaxf(acc2[rb][nt][2] + b2p[c0],     0.0f);
                    acc2[rb][nt][3] = fmaxf(acc2[rb][nt][3] + b2p[c0 + 1], 0.0f);
                    ssA += acc2[rb][nt][0] * acc2[rb][nt][0] + acc2[rb][nt][1] * acc2[rb][nt][1];
                    ssB += acc2[rb][nt][2] * acc2[rb][nt][2] + acc2[rb][nt][3] * acc2[rb][nt][3];
                }
                ssA += __shfl_xor_sync(0xffffffffu, ssA, 1);
                ssA += __shfl_xor_sync(0xffffffffu, ssA, 2);
                ssB += __shfl_xor_sync(0xffffffffu, ssB, 1);
                ssB += __shfl_xor_sync(0xffffffffu, ssB, 2);
                float invA = 1.0f / fmaxf(sqrtf(ssA), 1e-12f);
                float invB = 1.0f / fmaxf(sqrtf(ssB), 1e-12f);
                float dA = 0.0f, dB = 0.0f;
                uint32_t base = (uint32_t)(((wid * 2 + rb) * 8) * 32 + lane) * 8u;
#pragma unroll
                for (int nt = 0; nt < 8; nt++) {
                    uint2 u = *(const uint2*)(smem + OFF_VEC + base + (uint32_t)nt * 256u);
                    float2 uA = __half22float2(*(__half2*)&u.x);
                    float2 uB = __half22float2(*(__half2*)&u.y);
                    dA += uA.x * acc2[rb][nt][0] + uA.y * acc2[rb][nt][1];
                    dB += uB.x * acc2[rb][nt][2] + uB.y * acc2[rb][nt][3];
                }
                dA *= invA;
                dB *= invB;
                dA += __shfl_xor_sync(0xffffffffu, dA, 1);
                dA += __shfl_xor_sync(0xffffffffu, dA, 2);
                dB += __shfl_xor_sync(0xffffffffu, dB, 1);
                dB += __shfl_xor_sync(0xffffffffu, dB, 2);
                if (tg == 0) {
                    int r = rowbase + rb * 16 + g;
                    out[r]     = dA;
                    out[r + 8] = dB;
                }
            }
        }
        __syncwarp();
    }
}

extern "C" void kernel_launch(void* const* d_in, const int* in_sizes, int n_in,
                              void* d_out, int out_size) {
    const int*   user_ids   = (const int*)d_in[0];
    const int*   item_ids   = (const int*)d_in[1];
    const float* user_table = (const float*)d_in[2];
    const float* item_table = (const float*)d_in[3];
    const float* uW1 = (const float*)d_in[4];
    const float* ub1 = (const float*)d_in[5];
    const float* uW2 = (const float*)d_in[6];
    const float* ub2 = (const float*)d_in[7];
    const float* iW1 = (const float*)d_in[8];
    const float* ib1 = (const float*)d_in[9];
    const float* iW2 = (const float*)d_in[10];
    const float* ib2 = (const float*)d_in[11];
    float* out = (float*)d_out;

    cudaFuncSetAttribute(twotower_kernel, cudaFuncAttributeMaxDynamicSharedMemorySize, SMEM_TOTAL);
    twotower_kernel<<<NCTAS, THREADS, SMEM_TOTAL>>>(
        user_ids, item_ids, user_table, item_table,
        uW1, ub1, uW2, ub2, iW1, ib1, iW2, ib2, out);
}

// round 17
// speedup vs baseline: 1.3068x; 1.0722x over previous
#include <cuda_runtime.h>
#include <cuda_fp16.h>
#include <cstdint>

// ============================================================================
// TwoTowerModel — independent-warp mma.sync, 32 rows/warp, GEMM1 with fp16
// accumulators (D regs ARE the packed hfrag), GEMM2 fp32 accum, coalesced
// gather, fp16 VEC, warp-parity tower stagger. (baseline sm_103 ISA)
// ============================================================================

static constexpr int BATCH   = 524288;
static constexpr int TILE    = 256;
static constexpr int NTILES  = BATCH / TILE;   // 2048
static constexpr int THREADS = 256;            // 8 warps x 32 rows
static constexpr int NCTAS   = 148;

// ---- shared memory layout (bytes) ----
static constexpr int OFF_XA   = 0;             // first-tower emb fp16 [256][64] swz, 32K
static constexpr int OFF_XB   = 32768;         // second-tower emb fp16, 32K
static constexpr int OFF_VEC  = 65536;         // first-tower normalized vec fp16, 32K
static constexpr int OFF_W1F  = 98304;         // W1 frags: [tower]*16K = 32K
static constexpr int OFF_W2F  = 131072;        // W2 frags: 32K
static constexpr int OFF_B1H  = 163840;        // half2[2][64] packed layer1 bias, 512B
static constexpr int OFF_B2   = 164352;        // float[2][64]
static constexpr int SMEM_TOTAL = 164864;

__device__ __forceinline__ uint32_t smem_u32(const void* p) {
    uint32_t a;
    asm("{ .reg .u64 t; cvta.to.shared.u64 t, %1; cvt.u32.u64 %0, t; }" : "=r"(a) : "l"(p));
    return a;
}
// f32-accum mma (GEMM2)
__device__ __forceinline__ void mma_f16(float* d, const uint32_t* a, uint32_t b0, uint32_t b1) {
    asm volatile("mma.sync.aligned.m16n8k16.row.col.f32.f16.f16.f32 "
        "{%0,%1,%2,%3}, {%4,%5,%6,%7}, {%8,%9}, {%0,%1,%2,%3};"
        : "+f"(d[0]), "+f"(d[1]), "+f"(d[2]), "+f"(d[3])
        : "r"(a[0]), "r"(a[1]), "r"(a[2]), "r"(a[3]), "r"(b0), "r"(b1));
}
// f16-accum mma (GEMM1): D = 2 packed regs (row g, row g+8)
__device__ __forceinline__ void mma_f16h(uint32_t* d, const uint32_t* a, uint32_t b0, uint32_t b1) {
    asm volatile("mma.sync.aligned.m16n8k16.row.col.f16.f16.f16.f16 "
        "{%0,%1}, {%2,%3,%4,%5}, {%6,%7}, {%0,%1};"
        : "+r"(d[0]), "+r"(d[1])
        : "r"(a[0]), "r"(a[1]), "r"(a[2]), "r"(a[3]), "r"(b0), "r"(b1));
}
__device__ __forceinline__ void ldm4(uint32_t* a, uint32_t addr) {
    asm volatile("ldmatrix.sync.aligned.m8n8.x4.shared.b16 {%0,%1,%2,%3}, [%4];"
        : "=r"(a[0]), "=r"(a[1]), "=r"(a[2]), "=r"(a[3]) : "r"(addr) : "memory");
}
__device__ __forceinline__ void lds128(uint32_t* q, uint32_t addr) {
    asm volatile("ld.shared.v4.b32 {%0,%1,%2,%3}, [%4];"
        : "=r"(q[0]), "=r"(q[1]), "=r"(q[2]), "=r"(q[3]) : "r"(addr));
}
__device__ __forceinline__ uint32_t packh2(float a, float b) {
    __half2 h = __floats2half2_rn(a, b);
    return *(uint32_t*)&h;
}
// fp16x2 bias-add + relu on packed pair
__device__ __forceinline__ uint32_t relub2(uint32_t x, uint32_t b) {
    __half2 v = __hadd2(*(__half2*)&x, *(__half2*)&b);
    v = __hmax2(v, __float2half2_rn(0.0f));
    return *(uint32_t*)&v;
}

__global__ __launch_bounds__(THREADS, 1)
void twotower_kernel(
    const int* __restrict__ user_ids, const int* __restrict__ item_ids,
    const float* __restrict__ user_table, const float* __restrict__ item_table,
    const float* __restrict__ uW1, const float* __restrict__ ub1,
    const float* __restrict__ uW2, const float* __restrict__ ub2,
    const float* __restrict__ iW1, const float* __restrict__ ib1,
    const float* __restrict__ iW2, const float* __restrict__ ib2,
    float* __restrict__ out)
{
    extern __shared__ char smem[];
    const uint32_t sb = smem_u32(smem);
    const int tid  = threadIdx.x;
    const int wid  = tid >> 5;
    const int lane = tid & 31;
    const int tg   = lane & 3;
    const int g    = lane >> 2;
    const int khalf = lane >> 4;

    // ============ stage weights as nt-paired mma B-fragments (fp16) ====
    for (int t = 0; t < 2; t++) {
        const float* gW1 = t ? iW1 : uW1;   // [64][128] row-major
        const float* gW2 = t ? iW2 : uW2;   // [128][64]
        const float* gb1 = t ? ib1 : ub1;
        const float* gb2 = t ? ib2 : ub2;
        for (int p = tid; p < 1024; p += THREADS) {       // W1: kt(4) x ntp(8) x lane(32)
            int kt = p >> 8, ntp = (p >> 5) & 7, ln = p & 31;
            int ltg = ln & 3, lg = ln >> 2;
            int k0 = kt * 16 + ltg * 2;
            uint32_t q[4];
#pragma unroll
            for (int s = 0; s < 2; s++) {
                int n = (2 * ntp + s) * 8 + lg;
                q[2 * s + 0] = packh2(__ldg(gW1 + k0 * 128 + n),       __ldg(gW1 + (k0 + 1) * 128 + n));
                q[2 * s + 1] = packh2(__ldg(gW1 + (k0 + 8) * 128 + n), __ldg(gW1 + (k0 + 9) * 128 + n));
            }
            *((uint4*)(smem + OFF_W1F + t * 16384) + p) = make_uint4(q[0], q[1], q[2], q[3]);
        }
        for (int p = tid; p < 1024; p += THREADS) {       // W2: kt(8) x ntp(4) x lane(32)
            int kt = p >> 7, ntp = (p >> 5) & 3, ln = p & 31;
            int ltg = ln & 3, lg = ln >> 2;
            int k0 = kt * 16 + ltg * 2;
            uint32_t q[4];
#pragma unroll
            for (int s = 0; s < 2; s++) {
                int n = (2 * ntp + s) * 8 + lg;
                q[2 * s + 0] = packh2(__ldg(gW2 + k0 * 64 + n),       __ldg(gW2 + (k0 + 1) * 64 + n));
                q[2 * s + 1] = packh2(__ldg(gW2 + (k0 + 8) * 64 + n), __ldg(gW2 + (k0 + 9) * 64 + n));
            }
            *((uint4*)(smem + OFF_W2F + t * 16384) + p) = make_uint4(q[0], q[1], q[2], q[3]);
        }
        if (tid < 64) {   // packed half2 layer-1 bias: idx = nt*4+tg -> (b[c0], b[c0+1])
            int nt = tid >> 2, ltg = tid & 3;
            int c0 = nt * 8 + ltg * 2;
            ((uint32_t*)(smem + OFF_B1H))[t * 64 + tid] = packh2(__ldg(gb1 + c0), __ldg(gb1 + c0 + 1));
        }
        if (tid < 64)  ((float*)(smem + OFF_B2))[t * 64 + tid] = __ldg(gb2 + tid);
    }
    __syncthreads();

    const int pf = wid & 1;                   // parity: which tower goes first
    const int* idsF = pf ? item_ids : user_ids;
    const int* idsS = pf ? user_ids : item_ids;
    const float* tblF = pf ? item_table : user_table;
    const float* tblS = pf ? user_table : item_table;
    const uint32_t wofF = pf ? 16384u : 0u;
    const uint32_t wofS = 16384u - wofF;
    const uint32_t b1hF = (uint32_t)pf * 256u, b1hS = 256u - b1hF;
    const int b2F = pf * 64, b2S = 64 - b2F;

    const int wrow0 = wid * 32;               // warp's 32-row slab base
    const int myrow = wrow0 + lane;           // id-resident row (1 id/lane)
    const int rg = lane >> 3;                 // coalesced gather: row-in-group-of-4
    const int gs = lane & 7;                  // 16B sector within 128B line
    const int lr0 = wrow0 + (lane & 15);      // ldmatrix source rows
    const int lr1 = lr0 + 16;
    const uint32_t l0b = (uint32_t)lr0 * 128, l1b = (uint32_t)lr1 * 128;
    const uint32_t l0x = (uint32_t)(lr0 & 7), l1x = (uint32_t)(lr1 & 7);

    // ---------------- prologue: stage tile0 first-tower rows + second id ----
    int tile = blockIdx.x;
    float4 stg[16];
    {
        int idf = __ldg(idsF + tile * TILE + myrow);
#pragma unroll
        for (int k = 0; k < 8; k++) {
            int idk = __shfl_sync(0xffffffffu, idf, k * 4 + rg);
            const float4* src = (const float4*)(tblF + (size_t)(uint32_t)idk * 64);
            stg[k]     = __ldg(src + gs);
            stg[k + 8] = __ldg(src + 8 + gs);
        }
    }
    int idS_hold = __ldg(idsS + tile * TILE + myrow);

    for (; tile < NTILES; tile += gridDim.x) {
        const int rowbase = tile * TILE;
        int tnext = tile + (int)gridDim.x;
        if (tnext >= NTILES) tnext = tile;    // harmless reload on last iteration

        // ---- 1. convert staged first-tower rows -> XA ----
#pragma unroll
        for (int j = 0; j < 16; j++) {
            int k = j & 7, half = j >> 3;
            int r = wrow0 + k * 4 + rg;
            float4 v = stg[half * 8 + k];
            uint32_t chunk = (uint32_t)(half * 4 + (gs >> 1));
            uint32_t ad = (uint32_t)r * 128 + ((chunk ^ (uint32_t)(r & 7)) << 4) + (uint32_t)(gs & 1) * 8;
            *(uint2*)(smem + OFF_XA + ad) = make_uint2(packh2(v.x, v.y), packh2(v.z, v.w));
        }
        __syncwarp();

        // ---- 2. issue second-tower gather ----
#pragma unroll
        for (int k = 0; k < 8; k++) {
            int idk = __shfl_sync(0xffffffffu, idS_hold, k * 4 + rg);
            const float4* src = (const float4*)(tblS + (size_t)(uint32_t)idk * 64);
            stg[k]     = __ldg(src + gs);
            stg[k + 8] = __ldg(src + 8 + gs);
        }
        // ---- 3. prefetch next-tile ids ----
        int idF_next = __ldg(idsF + tnext * TILE + myrow);
        int idS_next = __ldg(idsS + tnext * TILE + myrow);

        uint32_t hfrag[2][8][4];
        float acc2[2][8][4];

        // ================= FIRST tower =================
        // ---- GEMM1 (fp16 accumulators; D regs are packed fragments) ----
#pragma unroll
        for (int h = 0; h < 2; h++) {
            uint32_t acc1h[2][8][2];
#pragma unroll
            for (int rb = 0; rb < 2; rb++)
#pragma unroll
                for (int i = 0; i < 8; i++) { acc1h[rb][i][0] = 0u; acc1h[rb][i][1] = 0u; }
#pragma unroll
            for (int kt = 0; kt < 4; kt++) {
                uint32_t A0[4], A1[4];
                uint32_t chg = (uint32_t)(kt * 2 + khalf);
                ldm4(A0, sb + OFF_XA + l0b + ((chg ^ l0x) << 4));
                ldm4(A1, sb + OFF_XA + l1b + ((chg ^ l1x) << 4));
                uint32_t wb = sb + OFF_W1F + wofF + ((uint32_t)((kt * 8 + h * 4) * 32 + lane)) * 16;
#pragma unroll
                for (int i = 0; i < 4; i++) {
                    uint32_t q[4];
                    lds128(q, wb + (uint32_t)i * 512);
                    mma_f16h(acc1h[0][2 * i],     A0, q[0], q[1]);
                    mma_f16h(acc1h[0][2 * i + 1], A0, q[2], q[3]);
                    mma_f16h(acc1h[1][2 * i],     A1, q[0], q[1]);
                    mma_f16h(acc1h[1][2 * i + 1], A1, q[2], q[3]);
                }
            }
            // ep1: packed bias-add + relu -> hfrag (2 instr per reg)
            const uint32_t* b1p = (const uint32_t*)(smem + OFF_B1H + b1hF);
#pragma unroll
            for (int rb = 0; rb < 2; rb++)
#pragma unroll
                for (int kp = 0; kp < 4; kp++) {
                    int lA = 2 * kp, lB = 2 * kp + 1;
                    uint32_t bA = b1p[(8 * h + lA) * 4 + tg];
                    uint32_t bB = b1p[(8 * h + lB) * 4 + tg];
                    hfrag[rb][4 * h + kp][0] = relub2(acc1h[rb][lA][0], bA);
                    hfrag[rb][4 * h + kp][1] = relub2(acc1h[rb][lA][1], bA);
                    hfrag[rb][4 * h + kp][2] = relub2(acc1h[rb][lB][0], bB);
                    hfrag[rb][4 * h + kp][3] = relub2(acc1h[rb][lB][1], bB);
                }
        }
        // ---- GEMM2 first (fp32 accum) ----
#pragma unroll
        for (int rb = 0; rb < 2; rb++)
#pragma unroll
            for (int i = 0; i < 8; i++)
#pragma unroll
                for (int j = 0; j < 4; j++) acc2[rb][i][j] = 0.0f;
#pragma unroll
        for (int kt = 0; kt < 8; kt++) {
            uint32_t wb = sb + OFF_W2F + wofF + ((uint32_t)(kt * 4 * 32 + lane)) * 16;
#pragma unroll
            for (int ntp = 0; ntp < 4; ntp++) {
                uint32_t q[4];
                lds128(q, wb + (uint32_t)ntp * 512);
                mma_f16(acc2[0][2 * ntp],     hfrag[0][kt], q[0], q[1]);
                mma_f16(acc2[0][2 * ntp + 1], hfrag[0][kt], q[2], q[3]);
                mma_f16(acc2[1][2 * ntp],     hfrag[1][kt], q[0], q[1]);
                mma_f16(acc2[1][2 * ntp + 1], hfrag[1][kt], q[2], q[3]);
            }
        }
        // ---- ep2 first: bias + relu + l2norm -> VEC (fp16 frag-linear) ----
        {
            const float* b2p = (const float*)(smem + OFF_B2) + b2F;
#pragma unroll
            for (int rb = 0; rb < 2; rb++) {
                float ssA = 0.0f, ssB = 0.0f;
#pragma unroll
                for (int nt = 0; nt < 8; nt++) {
                    int c0 = nt * 8 + tg * 2;
                    acc2[rb][nt][0] = fmaxf(acc2[rb][nt][0] + b2p[c0],     0.0f);
                    acc2[rb][nt][1] = fmaxf(acc2[rb][nt][1] + b2p[c0 + 1], 0.0f);
                    acc2[rb][nt][2] = fmaxf(acc2[rb][nt][2] + b2p[c0],     0.0f);
                    acc2[rb][nt][3] = fmaxf(acc2[rb][nt][3] + b2p[c0 + 1], 0.0f);
                    ssA += acc2[rb][nt][0] * acc2[rb][nt][0] + acc2[rb][nt][1] * acc2[rb][nt][1];
                    ssB += acc2[rb][nt][2] * acc2[rb][nt][2] + acc2[rb][nt][3] * acc2[rb][nt][3];
                }
                ssA += __shfl_xor_sync(0xffffffffu, ssA, 1);
                ssA += __shfl_xor_sync(0xffffffffu, ssA, 2);
                ssB += __shfl_xor_sync(0xffffffffu, ssB, 1);
                ssB += __shfl_xor_sync(0xffffffffu, ssB, 2);
                float invA = 1.0f / fmaxf(sqrtf(ssA), 1e-12f);
                float invB = 1.0f / fmaxf(sqrtf(ssB), 1e-12f);
                uint32_t base = (uint32_t)(((wid * 2 + rb) * 8) * 32 + lane) * 8u;
#pragma unroll
                for (int nt = 0; nt < 8; nt++) {
                    uint2 v = make_uint2(packh2(acc2[rb][nt][0] * invA, acc2[rb][nt][1] * invA),
                                         packh2(acc2[rb][nt][2] * invB, acc2[rb][nt][3] * invB));
                    *(uint2*)(smem + OFF_VEC + base + (uint32_t)nt * 256u) = v;
                }
            }
        }
        __syncwarp();

        // ---- 5. convert second-tower rows -> XB; staging freed ----
#pragma unroll
        for (int j = 0; j < 16; j++) {
            int k = j & 7, half = j >> 3;
            int r = wrow0 + k * 4 + rg;
            float4 v = stg[half * 8 + k];
            uint32_t chunk = (uint32_t)(half * 4 + (gs >> 1));
            uint32_t ad = (uint32_t)r * 128 + ((chunk ^ (uint32_t)(r & 7)) << 4) + (uint32_t)(gs & 1) * 8;
            *(uint2*)(smem + OFF_XB + ad) = make_uint2(packh2(v.x, v.y), packh2(v.z, v.w));
        }
        __syncwarp();

        // ---- 6. issue next-tile first-tower gather ----
#pragma unroll
        for (int k = 0; k < 8; k++) {
            int idk = __shfl_sync(0xffffffffu, idF_next, k * 4 + rg);
            const float4* src = (const float4*)(tblF + (size_t)(uint32_t)idk * 64);
            stg[k]     = __ldg(src + gs);
            stg[k + 8] = __ldg(src + 8 + gs);
        }

        // ================= SECOND tower =================
#pragma unroll
        for (int h = 0; h < 2; h++) {
            uint32_t acc1h[2][8][2];
#pragma unroll
            for (int rb = 0; rb < 2; rb++)
#pragma unroll
                for (int i = 0; i < 8; i++) { acc1h[rb][i][0] = 0u; acc1h[rb][i][1] = 0u; }
#pragma unroll
            for (int kt = 0; kt < 4; kt++) {
                uint32_t A0[4], A1[4];
                uint32_t chg = (uint32_t)(kt * 2 + khalf);
                ldm4(A0, sb + OFF_XB + l0b + ((chg ^ l0x) << 4));
                ldm4(A1, sb + OFF_XB + l1b + ((chg ^ l1x) << 4));
                uint32_t wb = sb + OFF_W1F + wofS + ((uint32_t)((kt * 8 + h * 4) * 32 + lane)) * 16;
#pragma unroll
                for (int i = 0; i < 4; i++) {
                    uint32_t q[4];
                    lds128(q, wb + (uint32_t)i * 512);
                    mma_f16h(acc1h[0][2 * i],     A0, q[0], q[1]);
                    mma_f16h(acc1h[0][2 * i + 1], A0, q[2], q[3]);
                    mma_f16h(acc1h[1][2 * i],     A1, q[0], q[1]);
                    mma_f16h(acc1h[1][2 * i + 1], A1, q[2], q[3]);
                }
            }
            const uint32_t* b1p = (const uint32_t*)(smem + OFF_B1H + b1hS);
#pragma unroll
            for (int rb = 0; rb < 2; rb++)
#pragma unroll
                for (int kp = 0; kp < 4; kp++) {
                    int lA = 2 * kp, lB = 2 * kp + 1;
                    uint32_t bA = b1p[(8 * h + lA) * 4 + tg];
                    uint32_t bB = b1p[(8 * h + lB) * 4 + tg];
                    hfrag[rb][4 * h + kp][0] = relub2(acc1h[rb][lA][0], bA);
                    hfrag[rb][4 * h + kp][1] = relub2(acc1h[rb][lA][1], bA);
                    hfrag[rb][4 * h + kp][2] = relub2(acc1h[rb][lB][0], bB);
                    hfrag[rb][4 * h + kp][3] = relub2(acc1h[rb][lB][1], bB);
                }
        }
        // ---- GEMM2 second ----
#pragma unroll
        for (int rb = 0; rb < 2; rb++)
#pragma unroll
            for (int i = 0; i < 8; i++)
#pragma unroll
                for (int j = 0; j < 4; j++) acc2[rb][i][j] = 0.0f;
#pragma unroll
        for (int kt = 0; kt < 8; kt++) {
            uint32_t wb = sb + OFF_W2F + wofS + ((uint32_t)(kt * 4 * 32 + lane)) * 16;
#pragma unroll
            for (int ntp = 0; ntp < 4; ntp++) {
                uint32_t q[4];
                lds128(q, wb + (uint32_t)ntp * 512);
                mma_f16(acc2[0][2 * ntp],     hfrag[0][kt], q[0], q[1]);
                mma_f16(acc2[0][2 * ntp + 1], hfrag[0][kt], q[2], q[3]);
                mma_f16(acc2[1][2 * ntp],     hfrag[1][kt], q[0], q[1]);
                mma_f16(acc2[1][2 * ntp + 1], hfrag[1][kt], q[2], q[3]);
            }
        }
        // ---- ep2 second: bias + relu + l2norm + dot(VEC fp16) + store ----
        {
            const float* b2p = (const float*)(smem + OFF_B2) + b2S;
#pragma unroll
            for (int rb = 0; rb < 2; rb++) {
                float ssA = 0.0f, ssB = 0.0f;
#pragma unroll
                for (int nt = 0; nt < 8; nt++) {
                    int c0 = nt * 8 + tg * 2;
                    acc2[rb][nt][0] = fmaxf(acc2[rb][nt][0] + b2p[c0],     0.0f);
                    acc2[rb][nt][1] = fmaxf(acc2[rb][nt][1] + b2p[c0 + 1], 0.0f);
                    acc2[rb][nt][2] = fmaxf(acc2[rb][nt][2] + b2p[c0],     0.0f);
                    acc2[rb][nt][3] = fmaxf(acc2[rb][nt][3] + b2p[c0 + 1], 0.0f);
                    ssA += acc2[rb][nt][0] * acc2[rb][nt][0] + acc2[rb][nt][1] * acc2[rb][nt][1];
                    ssB += acc2[rb][nt][2] * acc2[rb][nt][2] + acc2[rb][nt][3] * acc2[rb][nt][3];
                }
                ssA += __shfl_xor_sync(0xffffffffu, ssA, 1);
                ssA += __shfl_xor_sync(0xffffffffu, ssA, 2);
                ssB += __shfl_xor_sync(0xffffffffu, ssB, 1);
                ssB += __shfl_xor_sync(0xffffffffu, ssB, 2);
                float invA = 1.0f / fmaxf(sqrtf(ssA), 1e-12f);
                float invB = 1.0f / fmaxf(sqrtf(ssB), 1e-12f);
                float dA = 0.0f, dB = 0.0f;
                uint32_t base = (uint32_t)(((wid * 2 + rb) * 8) * 32 + lane) * 8u;
#pragma unroll
                for (int nt = 0; nt < 8; nt++) {
                    uint2 u = *(const uint2*)(smem + OFF_VEC + base + (uint32_t)nt * 256u);
                    float2 uA = __half22float2(*(__half2*)&u.x);
                    float2 uB = __half22float2(*(__half2*)&u.y);
                    dA += uA.x * acc2[rb][nt][0] + uA.y * acc2[rb][nt][1];
                    dB += uB.x * acc2[rb][nt][2] + uB.y * acc2[rb][nt][3];
                }
                dA *= invA;
                dB *= invB;
                dA += __shfl_xor_sync(0xffffffffu, dA, 1);
                dA += __shfl_xor_sync(0xffffffffu, dA, 2);
                dB += __shfl_xor_sync(0xffffffffu, dB, 1);
                dB += __shfl_xor_sync(0xffffffffu, dB, 2);
                if (tg == 0) {
                    int r = rowbase + wrow0 + rb * 16 + g;
                    out[r]     = dA;
                    out[r + 8] = dB;
                }
            }
        }
        idS_hold = idS_next;
        __syncwarp();
    }
}

extern "C" void kernel_launch(void* const* d_in, const int* in_sizes, int n_in,
                              void* d_out, int out_size) {
    const int*   user_ids   = (const int*)d_in[0];
    const int*   item_ids   = (const int*)d_in[1];
    const float* user_table = (const float*)d_in[2];
    const float* item_table = (const float*)d_in[3];
    const float* uW1 = (const float*)d_in[4];
    const float* ub1 = (const float*)d_in[5];
    const float* uW2 = (const float*)d_in[6];
    const float* ub2 = (const float*)d_in[7];
    const float* iW1 = (const float*)d_in[8];
    const float* ib1 = (const float*)d_in[9];
    const float* iW2 = (const float*)d_in[10];
    const float* ib2 = (const float*)d_in[11];
    float* out = (float*)d_out;

    cudaFuncSetAttribute(twotower_kernel, cudaFuncAttributeMaxDynamicSharedMemorySize, SMEM_TOTAL);
    twotower_kernel<<<NCTAS, THREADS, SMEM_TOTAL>>>(
        user_ids, item_ids, user_table, item_table,
        uW1, ub1, uW2, ub2, iW1, ib1, iW2, ib2, out);
}